// round 1
// baseline (speedup 1.0000x reference)
#include <cuda_runtime.h>
#include <cfloat>

// Problem shapes (fixed by the dataset)
#define BATCH   2
#define NBAND   40
#define NC      64      // channels per code / per x row
#define NT      1500    // time
#define NCODE   1024    // codes per band
#define TT      128     // time tile per CTA
#define KB      128     // code block per smem stage
#define THREADS 256     // 8 warps
#define CS_GS   65      // padded stride for the output-gather stage

// 0.5 * ||c_k||^2 per (band, code). Device scratch (no allocations allowed).
__device__ float g_cnorm[NBAND * NCODE];

__global__ void cnorm_kernel(const float* __restrict__ cb) {
    int i = blockIdx.x * blockDim.x + threadIdx.x;
    if (i >= NBAND * NCODE) return;
    const float4* row = reinterpret_cast<const float4*>(cb + (size_t)i * NC);
    float s = 0.f;
#pragma unroll
    for (int j = 0; j < NC / 4; j++) {
        float4 v = row[j];
        s += v.x * v.x + v.y * v.y + v.z * v.z + v.w * v.w;
    }
    g_cnorm[i] = 0.5f * s;
}

__global__ __launch_bounds__(THREADS, 2)
void vq_kernel(const float* __restrict__ x, const float* __restrict__ cb,
               float* __restrict__ out) {
    extern __shared__ float sm[];
    float* xs = sm;                    // [NC][TT]  x tile, t contiguous
    float* cs = xs + NC * TT;          // [KB][NC]  code block (also reused for gather, stride CS_GS)
    float* ns = cs + TT * CS_GS;       // [KB]      0.5*||c||^2
    float* rv = ns + KB;               // [16][TT]  reduction values
    int*   ri = (int*)(rv + 16 * TT);  // [16][TT]  reduction indices
    int*   bk = ri + 16 * TT;          // [TT]      winning code per t

    const int tile = blockIdx.x;
    const int bb   = blockIdx.y;           // b * NBAND + band
    const int band = bb % NBAND;
    const int t0   = tile * TT;
    const int tc   = min(TT, NT - t0);

    const float* xg = x  + (size_t)bb * NC * NT;
    const float* cg = cb + (size_t)band * NCODE * NC;

    // Load x tile: xs[c][tl] = x[b,band,c,t0+tl]; zero-pad the tail.
    for (int idx = threadIdx.x; idx < NC * TT; idx += THREADS) {
        int c = idx >> 7, tl = idx & (TT - 1);
        xs[idx] = (tl < tc) ? xg[c * NT + t0 + tl] : 0.f;
    }

    const int tx = threadIdx.x & 15;   // t group: pairs at 2*tx + 32*p
    const int ky = threadIdx.x >> 4;   // k group: 8 codes at k0 = 8*ky
    const int k0 = ky * 8;

    float bval[8];
    int   bidx[8];
#pragma unroll
    for (int r = 0; r < 8; r++) { bval[r] = -FLT_MAX; bidx[r] = 0; }

    for (int kb = 0; kb < NCODE; kb += KB) {
        __syncthreads();  // previous block fully consumed (and x tile ready on iter 0)
        for (int idx = threadIdx.x; idx < KB * NC; idx += THREADS)
            cs[idx] = cg[kb * NC + idx];
        if (threadIdx.x < KB)
            ns[threadIdx.x] = g_cnorm[band * NCODE + kb + threadIdx.x];
        __syncthreads();

        // 8t x 8k micro-tile, t packed into f32x2 pairs.
        unsigned long long acc[4][8];
#pragma unroll
        for (int p = 0; p < 4; p++)
#pragma unroll
            for (int j = 0; j < 8; j++) acc[p][j] = 0ULL;

#pragma unroll 2
        for (int c2 = 0; c2 < NC / 2; c2++) {
            float2 cv[8];
#pragma unroll
            for (int j = 0; j < 8; j++)
                cv[j] = *reinterpret_cast<const float2*>(&cs[(k0 + j) * NC + 2 * c2]);
#pragma unroll
            for (int cc = 0; cc < 2; cc++) {
                const float* xrow = &xs[(2 * c2 + cc) * TT + 2 * tx];
                unsigned long long xp[4];
#pragma unroll
                for (int p = 0; p < 4; p++)
                    xp[p] = *reinterpret_cast<const unsigned long long*>(xrow + 32 * p);
#pragma unroll
                for (int j = 0; j < 8; j++) {
                    unsigned int cu = __float_as_uint(cc == 0 ? cv[j].x : cv[j].y);
                    unsigned long long cp;
                    asm("mov.b64 %0, {%1, %1};" : "=l"(cp) : "r"(cu));
#pragma unroll
                    for (int p = 0; p < 4; p++)
                        asm("fma.rn.f32x2 %0, %1, %2, %0;"
                            : "+l"(acc[p][j]) : "l"(xp[p]), "l"(cp));
                }
            }
        }

        // score = x.c - 0.5||c||^2 ; running argmax with first-occurrence ties
        // (k strictly increases within a thread, so strict '>' keeps the earliest).
#pragma unroll
        for (int j = 0; j < 8; j++) {
            float nsj = ns[k0 + j];
            int   kk  = kb + k0 + j;
#pragma unroll
            for (int p = 0; p < 4; p++) {
                unsigned int lo, hi;
                asm("mov.b64 {%0, %1}, %2;" : "=r"(lo), "=r"(hi) : "l"(acc[p][j]));
                float s0 = __uint_as_float(lo) - nsj;
                float s1 = __uint_as_float(hi) - nsj;
                if (s0 > bval[2 * p])     { bval[2 * p]     = s0; bidx[2 * p]     = kk; }
                if (s1 > bval[2 * p + 1]) { bval[2 * p + 1] = s1; bidx[2 * p + 1] = kk; }
            }
        }
    }

    // Cross-thread (over ky) argmax reduction per t.
    __syncthreads();
#pragma unroll
    for (int p = 0; p < 4; p++)
#pragma unroll
        for (int e = 0; e < 2; e++) {
            int tloc = 32 * p + 2 * tx + e;
            rv[ky * TT + tloc] = bval[2 * p + e];
            ri[ky * TT + tloc] = bidx[2 * p + e];
        }
    __syncthreads();
    if (threadIdx.x < TT) {
        int tl = threadIdx.x;
        float bv = rv[tl]; int bi = ri[tl];
#pragma unroll
        for (int y = 1; y < 16; y++) {
            float v = rv[y * TT + tl]; int ix = ri[y * TT + tl];
            if (v > bv || (v == bv && ix < bi)) { bv = v; bi = ix; }
        }
        bk[tl] = bi;
    }
    __syncthreads();

    // Gather winning code rows into smem (coalesced global reads) ...
    for (int idx = threadIdx.x; idx < TT * NC; idx += THREADS) {
        int tl = idx >> 6, c = idx & 63;
        cs[tl * CS_GS + c] = cg[(size_t)bk[tl] * NC + c];
    }
    __syncthreads();
    // ... then write out[b,band,c,t] coalesced along t.
    float* og = out + (size_t)bb * NC * NT;
    for (int idx = threadIdx.x; idx < NC * TT; idx += THREADS) {
        int c = idx >> 7, tl = idx & (TT - 1);
        if (tl < tc) og[c * NT + t0 + tl] = cs[tl * CS_GS + c];
    }
}

extern "C" void kernel_launch(void* const* d_in, const int* in_sizes, int n_in,
                              void* d_out, int out_size) {
    const float* x  = (const float*)d_in[0];   // (2, 40, 64, 1500) f32
    const float* cb = (const float*)d_in[1];   // (40, 1024, 64) f32
    float* out = (float*)d_out;                // (2, 40, 64, 1500) f32

    cnorm_kernel<<<(NBAND * NCODE + 255) / 256, 256>>>(cb);

    const size_t smem_bytes =
        (size_t)(NC * TT + TT * CS_GS + KB + 16 * TT + 16 * TT + TT) * sizeof(float);
    cudaFuncSetAttribute(vq_kernel, cudaFuncAttributeMaxDynamicSharedMemorySize,
                         (int)smem_bytes);

    dim3 grid((NT + TT - 1) / TT, BATCH * NBAND);
    vq_kernel<<<grid, THREADS, smem_bytes>>>(x, cb, out);
}